// round 1
// baseline (speedup 1.0000x reference)
#include <cuda_runtime.h>

// bg:  (1, 4, 32, 32, 32, 16) fp32   [c][h][w][d][t], c stride = 524288
// gm:  (1, 1, 128, 128, 128) fp32
// out: (1, 4, 128, 128, 128) fp32
//
// Kernel 1: transpose bg -> bgT[h][w][d][t][c] (channel-innermost, float4-able)
// Kernel 2: per-voxel quadrilinear slice, 16 corners x LDG.128 over channels.

#define BG_H 32
#define BG_W 32
#define BG_D 32
#define BG_T 16
#define BG_C 4
#define GSZ 128
#define G3 (GSZ * GSZ * GSZ)
#define BG_SPATIAL (BG_H * BG_W * BG_D * BG_T)   // 524288
#define CH_STRIDE  BG_SPATIAL                     // per-channel stride in bg

// 8 MB static scratch for transposed grid: index = (((h*32+w)*32+d)*16+t)*4 + c
__device__ float g_bgT[BG_SPATIAL * BG_C];

__global__ __launch_bounds__(256) void transpose_kernel(const float* __restrict__ bg) {
    int idx = blockIdx.x * blockDim.x + threadIdx.x;   // over h*w*d*t
    if (idx >= BG_SPATIAL) return;
    float4 v;
    v.x = bg[idx];
    v.y = bg[idx + CH_STRIDE];
    v.z = bg[idx + 2 * CH_STRIDE];
    v.w = bg[idx + 3 * CH_STRIDE];
    reinterpret_cast<float4*>(g_bgT)[idx] = v;
}

__device__ __forceinline__ void prep_axis(float coord, int sz, int& i0, int& i1, float& fr) {
    // mirror reference: clip -> floor -> frac, i1 = min(i0+1, sz-1)
    coord = fminf(fmaxf(coord, 0.0f), (float)(sz - 1));
    float f = floorf(coord);
    fr = coord - f;
    i0 = (int)f;
    i1 = min(i0 + 1, sz - 1);
}

__global__ __launch_bounds__(512) void slice_kernel(const float* __restrict__ gm,
                                                    float* __restrict__ out) {
    int gd = blockIdx.x * 32 + threadIdx.x;   // innermost -> coalesced
    int gw = blockIdx.y * 4 + threadIdx.y;
    int gh = blockIdx.z * 4 + threadIdx.z;

    const float sx = 31.0f / 127.0f;   // (h-1)/(gh-1), same fp ops as reference

    int x0, x1, y0, y1, z0, z1, t0, t1;
    float fx, fy, fz, ft;
    prep_axis((float)gh * sx, BG_H, x0, x1, fx);
    prep_axis((float)gw * sx, BG_W, y0, y1, fy);
    prep_axis((float)gd * sx, BG_D, z0, z1, fz);

    int gidx = (gh * GSZ + gw) * GSZ + gd;
    float tval = gm[gidx] * 15.0f;            // (up-1)
    prep_axis(tval, BG_T, t0, t1, ft);

    float wt0 = 1.0f - ft;
    float wt1 = ft;

    int   xi[2] = {x0, x1};
    int   yi[2] = {y0, y1};
    int   zi[2] = {z0, z1};
    float wxa[2] = {1.0f - fx, fx};
    float wya[2] = {1.0f - fy, fy};
    float wza[2] = {1.0f - fz, fz};

    const float4* __restrict__ B = reinterpret_cast<const float4*>(g_bgT);

    float ax = 0.f, ay = 0.f, az = 0.f, aw = 0.f;

#pragma unroll
    for (int ix = 0; ix < 2; ix++) {
        int xoff = xi[ix] * (BG_W * BG_D * BG_T);
        float wx = wxa[ix];
#pragma unroll
        for (int iy = 0; iy < 2; iy++) {
            int xyoff = xoff + yi[iy] * (BG_D * BG_T);
            float wxy = wx * wya[iy];
#pragma unroll
            for (int iz = 0; iz < 2; iz++) {
                int base = xyoff + zi[iz] * BG_T;   // float4 index
                float w = wxy * wza[iz];
                float4 v0 = B[base + t0];
                float4 v1 = B[base + t1];
                float wa = w * wt0;
                float wb = w * wt1;
                ax = fmaf(wa, v0.x, ax); ax = fmaf(wb, v1.x, ax);
                ay = fmaf(wa, v0.y, ay); ay = fmaf(wb, v1.y, ay);
                az = fmaf(wa, v0.z, az); az = fmaf(wb, v1.z, az);
                aw = fmaf(wa, v0.w, aw); aw = fmaf(wb, v1.w, aw);
            }
        }
    }

    out[gidx]          = ax;
    out[gidx + G3]     = ay;
    out[gidx + 2 * G3] = az;
    out[gidx + 3 * G3] = aw;
}

extern "C" void kernel_launch(void* const* d_in, const int* in_sizes, int n_in,
                              void* d_out, int out_size) {
    const float* bg = (const float*)d_in[0];
    const float* gm = (const float*)d_in[1];
    float* out = (float*)d_out;

    transpose_kernel<<<(BG_SPATIAL + 255) / 256, 256>>>(bg);

    dim3 block(32, 4, 4);                      // gd, gw, gh
    dim3 grid(GSZ / 32, GSZ / 4, GSZ / 4);     // (4, 32, 32)
    slice_kernel<<<grid, block>>>(gm, out);
}

// round 3
// speedup vs baseline: 1.3038x; 1.3038x over previous
#include <cuda_runtime.h>

// bg:  (1, 4, 32, 32, 32, 16) fp32   [c][h][w][d][t], c stride = 524288
// gm:  (1, 1, 128, 128, 128) fp32
// out: (1, 4, 128, 128, 128) fp32
//
// Kernel 1: transpose bg -> bgT[h][w][d][t][c] (channel-innermost float4)
// Kernel 2: per-(gh,gw)-column: build xy-interpolated plane P[z][t] (float4 over c)
//           in smem (coalesced global reads), then each voxel gathers only
//           2z x 2t = 4 LDS.128 from smem.

#define BG_H 32
#define BG_W 32
#define BG_D 32
#define BG_T 16
#define BG_C 4
#define GSZ 128
#define G3 (GSZ * GSZ * GSZ)
#define BG_SPATIAL (BG_H * BG_W * BG_D * BG_T)   // 524288
#define CH_STRIDE  BG_SPATIAL
#define ZT 512                                    // 32 z * 16 t entries per (x,y) row

__device__ float g_bgT[BG_SPATIAL * BG_C];        // [h][w][z][t][c], 8 MB scratch

__global__ __launch_bounds__(256) void transpose_kernel(const float* __restrict__ bg) {
    int idx = blockIdx.x * blockDim.x + threadIdx.x;   // over h*w*d*t
    if (idx >= BG_SPATIAL) return;
    float4 v;
    v.x = bg[idx];
    v.y = bg[idx + CH_STRIDE];
    v.z = bg[idx + 2 * CH_STRIDE];
    v.w = bg[idx + 3 * CH_STRIDE];
    reinterpret_cast<float4*>(g_bgT)[idx] = v;
}

__device__ __forceinline__ void prep_axis(float coord, int sz, int& i0, int& i1, float& fr) {
    // mirror reference: clip -> floor -> frac, i1 = min(i0+1, sz-1)
    coord = fminf(fmaxf(coord, 0.0f), (float)(sz - 1));
    float f = floorf(coord);
    fr = coord - f;
    i0 = (int)f;
    i1 = min(i0 + 1, sz - 1);
}

// block (128, 2, 2): tx = gd (full column), (ty,tz) = 2x2 (gw,gh) tile
__global__ __launch_bounds__(512) void slice_kernel(const float* __restrict__ gm,
                                                    float* __restrict__ out) {
    __shared__ float4 P[4][ZT];                     // 32 KB: per-column xy-plane

    int tx = threadIdx.x;                           // gd
    int ty = threadIdx.y;                           // gw sub
    int tz = threadIdx.z;                           // gh sub
    int col = tz * 2 + ty;

    int gd = tx;
    int gw = blockIdx.y * 2 + ty;
    int gh = blockIdx.z * 2 + tz;

    const float s = 31.0f / 127.0f;

    // ---- per-column xy params (uniform across the 128 tx threads of a column)
    int x0, x1, y0, y1;
    float fx, fy;
    prep_axis((float)gh * s, BG_H, x0, x1, fx);
    prep_axis((float)gw * s, BG_W, y0, y1, fy);

    float w00 = (1.0f - fx) * (1.0f - fy);
    float w01 = (1.0f - fx) * fy;
    float w10 = fx * (1.0f - fy);
    float w11 = fx * fy;

    const float4* __restrict__ B = reinterpret_cast<const float4*>(g_bgT);
    const float4* r00 = B + (x0 * BG_W + y0) * ZT;
    const float4* r01 = B + (x0 * BG_W + y1) * ZT;
    const float4* r10 = B + (x1 * BG_W + y0) * ZT;
    const float4* r11 = B + (x1 * BG_W + y1) * ZT;

    // ---- cooperative P build: 128 threads per column, 4 elements each
#pragma unroll
    for (int k = 0; k < 4; k++) {
        int e = tx + 128 * k;                       // coalesced over warp
        float4 a = __ldg(r00 + e);
        float4 b = __ldg(r01 + e);
        float4 cc = __ldg(r10 + e);
        float4 d = __ldg(r11 + e);
        float4 p;
        p.x = fmaf(w11, d.x, fmaf(w10, cc.x, fmaf(w01, b.x, w00 * a.x)));
        p.y = fmaf(w11, d.y, fmaf(w10, cc.y, fmaf(w01, b.y, w00 * a.y)));
        p.z = fmaf(w11, d.z, fmaf(w10, cc.z, fmaf(w01, b.z, w00 * a.z)));
        p.w = fmaf(w11, d.w, fmaf(w10, cc.w, fmaf(w01, b.w, w00 * a.w)));
        P[col][e] = p;
    }
    __syncthreads();

    // ---- per-voxel gather: 2z x 2t from smem
    int z0, z1, t0, t1;
    float fz, ft;
    prep_axis((float)gd * s, BG_D, z0, z1, fz);

    int gidx = (gh * GSZ + gw) * GSZ + gd;
    float tval = gm[gidx] * 15.0f;
    prep_axis(tval, BG_T, t0, t1, ft);

    float wz0 = 1.0f - fz, wz1 = fz;
    float wt0 = 1.0f - ft, wt1 = ft;
    float w_00 = wz0 * wt0;
    float w_01 = wz0 * wt1;
    float w_10 = wz1 * wt0;
    float w_11 = wz1 * wt1;

    const float4* Pc = P[col];
    float4 v00 = Pc[z0 * BG_T + t0];
    float4 v01 = Pc[z0 * BG_T + t1];
    float4 v10 = Pc[z1 * BG_T + t0];
    float4 v11 = Pc[z1 * BG_T + t1];

    float ax, ay, az, aw;
    ax = w_00 * v00.x; ay = w_00 * v00.y; az = w_00 * v00.z; aw = w_00 * v00.w;
    ax = fmaf(w_01, v01.x, ax); ay = fmaf(w_01, v01.y, ay);
    az = fmaf(w_01, v01.z, az); aw = fmaf(w_01, v01.w, aw);
    ax = fmaf(w_10, v10.x, ax); ay = fmaf(w_10, v10.y, ay);
    az = fmaf(w_10, v10.z, az); aw = fmaf(w_10, v10.w, aw);
    ax = fmaf(w_11, v11.x, ax); ay = fmaf(w_11, v11.y, ay);
    az = fmaf(w_11, v11.z, az); aw = fmaf(w_11, v11.w, aw);

    out[gidx]          = ax;
    out[gidx + G3]     = ay;
    out[gidx + 2 * G3] = az;
    out[gidx + 3 * G3] = aw;
}

extern "C" void kernel_launch(void* const* d_in, const int* in_sizes, int n_in,
                              void* d_out, int out_size) {
    const float* bg = (const float*)d_in[0];
    const float* gm = (const float*)d_in[1];
    float* out = (float*)d_out;

    transpose_kernel<<<(BG_SPATIAL + 255) / 256, 256>>>(bg);

    dim3 block(128, 2, 2);                 // gd, gw, gh
    dim3 grid(1, GSZ / 2, GSZ / 2);        // (1, 64, 64)
    slice_kernel<<<grid, block>>>(gm, out);
}

// round 4
// speedup vs baseline: 1.3692x; 1.0502x over previous
#include <cuda_runtime.h>

// bg:  (1, 4, 32, 32, 32, 16) fp32  laid out [c][x][y][z][t]
//      row (x,y) for channel c = 512 contiguous floats at bg[c*524288 + (x*32+y)*512]
// gm:  (1, 1, 128, 128, 128) fp32
// out: (1, 4, 128, 128, 128) fp32
//
// Single kernel. Per (gh,gw) column: build xy-interpolated plane P[z][t] (float4
// over channels) in smem directly from bg (16 coalesced scalar streams), then
// each voxel gathers 2z x 2t = 4 LDS.128.

#define BG_WDT 512            // z*t entries per (x,y,c) row
#define CH 524288             // channel stride in bg
#define GSZ 128
#define G3 (GSZ * GSZ * GSZ)
#define BG_T 16

__device__ __forceinline__ void prep_axis(float coord, int sz, int& i0, int& i1, float& fr) {
    // mirror reference: clip -> floor -> frac, i1 = min(i0+1, sz-1)
    coord = fminf(fmaxf(coord, 0.0f), (float)(sz - 1));
    float f = floorf(coord);
    fr = coord - f;
    i0 = (int)f;
    i1 = min(i0 + 1, sz - 1);
}

// block = 256 threads = 2 columns x 128 voxels. grid = (64, 128) -> (gw/2, gh)
__global__ __launch_bounds__(256, 8) void slice_kernel(const float* __restrict__ bg,
                                                       const float* __restrict__ gm,
                                                       float* __restrict__ out) {
    __shared__ float4 P[2][BG_WDT];                 // 16 KB

    int tid  = threadIdx.x;
    int col  = tid >> 7;                            // 0..1
    int tcol = tid & 127;                           // voxel gd / build lane

    int gw = blockIdx.x * 2 + col;
    int gh = blockIdx.y;
    int gd = tcol;

    const float s = 31.0f / 127.0f;

    // ---- per-column xy params (uniform across the column's 128 threads)
    int x0, x1, y0, y1;
    float fx, fy;
    prep_axis((float)gh * s, 32, x0, x1, fx);
    prep_axis((float)gw * s, 32, y0, y1, fy);

    float w00 = (1.0f - fx) * (1.0f - fy);
    float w01 = (1.0f - fx) * fy;
    float w10 = fx * (1.0f - fy);
    float w11 = fx * fy;

    const float* b00 = bg + (x0 * 32 + y0) * BG_WDT;
    const float* b01 = bg + (x0 * 32 + y1) * BG_WDT;
    const float* b10 = bg + (x1 * 32 + y0) * BG_WDT;
    const float* b11 = bg + (x1 * 32 + y1) * BG_WDT;

    // ---- cooperative P build: 128 threads per column, 4 entries each.
    // Reads original bg layout: per (row, channel) a 2KB contiguous run -> coalesced.
#pragma unroll
    for (int k = 0; k < 4; k++) {
        int e = tcol + 128 * k;
        float4 p;
        p.x = fmaf(w11, b11[e], fmaf(w10, b10[e], fmaf(w01, b01[e], w00 * b00[e])));
        p.y = fmaf(w11, b11[e + CH], fmaf(w10, b10[e + CH],
              fmaf(w01, b01[e + CH], w00 * b00[e + CH])));
        p.z = fmaf(w11, b11[e + 2 * CH], fmaf(w10, b10[e + 2 * CH],
              fmaf(w01, b01[e + 2 * CH], w00 * b00[e + 2 * CH])));
        p.w = fmaf(w11, b11[e + 3 * CH], fmaf(w10, b10[e + 3 * CH],
              fmaf(w01, b01[e + 3 * CH], w00 * b00[e + 3 * CH])));
        P[col][e] = p;
    }
    __syncthreads();

    // ---- per-voxel gather: 2z x 2t from smem, low register pressure
    int z0, z1, t0, t1;
    float fz, ft;
    prep_axis((float)gd * s, 32, z0, z1, fz);

    int gidx = (gh * GSZ + gw) * GSZ + gd;
    float tval = gm[gidx] * 15.0f;
    prep_axis(tval, BG_T, t0, t1, ft);

    float wz0 = 1.0f - fz, wz1 = fz;
    float wt0 = 1.0f - ft, wt1 = ft;
    float w_00 = wz0 * wt0;
    float w_01 = wz0 * wt1;
    float w_10 = wz1 * wt0;
    float w_11 = wz1 * wt1;

    const float4* Pc = P[col];

    float ax, ay, az, aw;
    {
        float4 v00 = Pc[z0 * BG_T + t0];
        float4 v01 = Pc[z0 * BG_T + t1];
        ax = fmaf(w_01, v01.x, w_00 * v00.x);
        ay = fmaf(w_01, v01.y, w_00 * v00.y);
        az = fmaf(w_01, v01.z, w_00 * v00.z);
        aw = fmaf(w_01, v01.w, w_00 * v00.w);
    }
    {
        float4 v10 = Pc[z1 * BG_T + t0];
        float4 v11 = Pc[z1 * BG_T + t1];
        ax = fmaf(w_11, v11.x, fmaf(w_10, v10.x, ax));
        ay = fmaf(w_11, v11.y, fmaf(w_10, v10.y, ay));
        az = fmaf(w_11, v11.z, fmaf(w_10, v10.z, az));
        aw = fmaf(w_11, v11.w, fmaf(w_10, v10.w, aw));
    }

    out[gidx]          = ax;
    out[gidx + G3]     = ay;
    out[gidx + 2 * G3] = az;
    out[gidx + 3 * G3] = aw;
}

extern "C" void kernel_launch(void* const* d_in, const int* in_sizes, int n_in,
                              void* d_out, int out_size) {
    const float* bg = (const float*)d_in[0];
    const float* gm = (const float*)d_in[1];
    float* out = (float*)d_out;

    dim3 block(256);
    dim3 grid(GSZ / 2, GSZ);          // (gw pairs, gh)
    slice_kernel<<<grid, block>>>(bg, gm, out);
}